// round 11
// baseline (speedup 1.0000x reference)
#include <cuda_runtime.h>
#include <cuda_bf16.h>
#include <cstdint>

#define NROWS 8192
#define DCOLS 512

// ---------------- scratch (device globals: allocation-free) ----------------
__device__ __align__(256) int8_t g_A1[(size_t)NROWS * NROWS];   // 64 MB
__device__ __align__(256) int8_t g_A2[(size_t)NROWS * NROWS];   // 64 MB
__device__ __align__(256) int8_t g_B1[(size_t)DCOLS * NROWS];   // 4 MB [n][k]
__device__ __align__(256) int8_t g_B2[(size_t)DCOLS * NROWS];   // 4 MB
__device__ __align__(256) int   g_part[(size_t)NROWS * DCOLS];  // 16 MB (a1*b1)
__device__ float g_deg[NROWS];
__device__ float g_Sa[NROWS];
__device__ float g_Sb[DCOLS];

// ---------------- PTX helpers (compute_100-safe: no 'a' features) ----------
__device__ __forceinline__ uint32_t smem_u32(const void* p) {
    uint32_t a;
    asm("{ .reg .u64 t; cvta.to.shared.u64 t, %1; cvt.u32.u64 %0, t; }" : "=r"(a) : "l"(p));
    return a;
}
__device__ __forceinline__ void cp16(uint32_t dst, const void* src) {
    asm volatile("cp.async.cg.shared.global [%0], [%1], 16;" :: "r"(dst), "l"(src));
}
__device__ __forceinline__ void ldsm4(uint32_t* r, uint32_t addr) {
    asm volatile("ldmatrix.sync.aligned.m8n8.x4.shared.b16 {%0,%1,%2,%3}, [%4];"
                 : "=r"(r[0]), "=r"(r[1]), "=r"(r[2]), "=r"(r[3]) : "r"(addr));
}
__device__ __forceinline__ void mma_s8(int* c, const uint32_t* a, const uint32_t* b) {
    asm("mma.sync.aligned.m16n8k32.row.col.s32.s8.s8.s32 "
        "{%0,%1,%2,%3}, {%4,%5,%6,%7}, {%8,%9}, {%0,%1,%2,%3};"
        : "+r"(c[0]), "+r"(c[1]), "+r"(c[2]), "+r"(c[3])
        : "r"(a[0]), "r"(a[1]), "r"(a[2]), "r"(a[3]), "r"(b[0]), "r"(b[1]));
}
__device__ __forceinline__ uint32_t pack4(int b0, int b1, int b2, int b3) {
    return (b0 & 0xFF) | ((b1 & 0xFF) << 8) | ((b2 & 0xFF) << 16) | ((b3 & 0xFF) << 24);
}

// ---------------- P1: row stats + XLA-order deg + int8 quant ----------------
__global__ void __launch_bounds__(256) prep_rows(const float* __restrict__ inc) {
    __shared__ float row[NROWS];
    __shared__ int   red_c[8];
    __shared__ float wpart[32];
    __shared__ float s_hv, s_inv;

    const int r = blockIdx.x;
    const int tid = threadIdx.x;
    const int lane = tid & 31, warp = tid >> 5;

    const float4* src = (const float4*)(inc + (size_t)r * NROWS);
    float4* dst = (float4*)row;
    int cnt = 0;
    for (int i = tid; i < NROWS / 4; i += 256) {
        float4 v = src[i];
        dst[i] = v;
        cnt += (v.x > 0.f) + (v.y > 0.f) + (v.z > 0.f) + (v.w > 0.f);
    }
    for (int o = 16; o; o >>= 1) cnt += __shfl_xor_sync(0xFFFFFFFFu, cnt, o);
    if (lane == 0) red_c[warp] = cnt;
    __syncthreads();
    if (tid == 0) {
        int c = 0;
        #pragma unroll
        for (int i = 0; i < 8; i++) c += red_c[i];
        float denom = __fsqrt_rn((float)c);
        denom = fmaxf(denom, 1e-12f);
        s_hv = __fdiv_rn(1.0f, denom);
    }
    __syncthreads();
    const float hv = s_hv;

    // deg: XLA-GPU row-reduce order mimic (1024 virtual threads on 256 real)
    float accx[4], accy[4];
    #pragma unroll
    for (int jv = 0; jv < 4; jv++) { accx[jv] = 0.f; accy[jv] = 0.f; }
    #pragma unroll
    for (int jv = 0; jv < 4; jv++) {
        const int vt = tid + 256 * jv;
        #pragma unroll
        for (int i = 0; i < 4; i++) {
            const int j = 2 * vt + 2048 * i;
            float x = row[j];
            float y = row[j + 1];
            if (x > 0.f) x = x + hv;
            if (y > 0.f) y = y + hv;
            accx[jv] += x;
            accy[jv] += y;
        }
    }
    #pragma unroll
    for (int jv = 0; jv < 4; jv++) {
        float s = accx[jv] + accy[jv];
        s += __shfl_down_sync(0xFFFFFFFFu, s, 16);
        s += __shfl_down_sync(0xFFFFFFFFu, s, 8);
        s += __shfl_down_sync(0xFFFFFFFFu, s, 4);
        s += __shfl_down_sync(0xFFFFFFFFu, s, 2);
        s += __shfl_down_sync(0xFFFFFFFFu, s, 1);
        if (lane == 0) wpart[jv * 8 + warp] = s;
    }
    __syncthreads();
    if (tid < 32) {
        float v = wpart[tid];
        v += __shfl_down_sync(0xFFFFFFFFu, v, 16);
        v += __shfl_down_sync(0xFFFFFFFFu, v, 8);
        v += __shfl_down_sync(0xFFFFFFFFu, v, 4);
        v += __shfl_down_sync(0xFFFFFFFFu, v, 2);
        v += __shfl_down_sync(0xFFFFFFFFu, v, 1);
        if (tid == 0) g_deg[r] = v;
    }
    __syncthreads();

    // row max of |a'|
    float mx = 0.f;
    for (int i = tid; i < NROWS / 4; i += 256) {
        float4 v = dst[i];
        float a0 = (v.x > 0.f) ? v.x + hv : v.x;
        float a1 = (v.y > 0.f) ? v.y + hv : v.y;
        float a2 = (v.z > 0.f) ? v.z + hv : v.z;
        float a3 = (v.w > 0.f) ? v.w + hv : v.w;
        mx = fmaxf(mx, fmaxf(fmaxf(fabsf(a0), fabsf(a1)), fmaxf(fabsf(a2), fabsf(a3))));
    }
    for (int o = 16; o; o >>= 1) mx = fmaxf(mx, __shfl_xor_sync(0xFFFFFFFFu, mx, o));
    if (lane == 0) wpart[warp] = mx;
    __syncthreads();
    if (tid == 0) {
        float m = 1e-30f;
        #pragma unroll
        for (int i = 0; i < 8; i++) m = fmaxf(m, wpart[i]);
        g_Sa[r] = m / 127.f;
        s_inv = 127.f / m;
    }
    __syncthreads();
    const float inv = s_inv;

    // quantize: a' = Sa*(q1 + q2/254)
    uint2* p1 = (uint2*)(g_A1 + (size_t)r * NROWS);
    uint2* p2 = (uint2*)(g_A2 + (size_t)r * NROWS);
    for (int i = tid; i < NROWS / 8; i += 256) {
        int q1[8], q2[8];
        #pragma unroll
        for (int e = 0; e < 8; e++) {
            float a = row[8 * i + e];
            if (a > 0.f) a = a + hv;
            float q = a * inv;
            int i1 = __float2int_rn(q);
            int i2 = __float2int_rn(254.f * (q - (float)i1));
            q1[e] = i1; q2[e] = i2;
        }
        uint2 u1, u2;
        u1.x = pack4(q1[0], q1[1], q1[2], q1[3]);
        u1.y = pack4(q1[4], q1[5], q1[6], q1[7]);
        u2.x = pack4(q2[0], q2[1], q2[2], q2[3]);
        u2.y = pack4(q2[4], q2[5], q2[6], q2[7]);
        p1[i] = u1;
        p2[i] = u2;
    }
}

// ---------------- P2a: per-column max of cur -> g_Sb ----------------
__global__ void __launch_bounds__(256) prep_Bscale(const float* __restrict__ cur) {
    __shared__ float red[32][8];
    const int tid = threadIdx.x;
    const int nIn = tid & 7;
    const int kp = tid >> 3;
    const int n = blockIdx.x * 8 + nIn;
    float m = 0.f;
    for (int k = kp; k < NROWS; k += 32)
        m = fmaxf(m, fabsf(cur[(size_t)k * DCOLS + n]));
    red[kp][nIn] = m;
    __syncthreads();
    if (tid < 8) {
        float mm = 1e-30f;
        #pragma unroll
        for (int i = 0; i < 32; i++) mm = fmaxf(mm, red[i][tid]);
        g_Sb[blockIdx.x * 8 + tid] = mm / 127.f;
    }
}

// ---------------- P2b: cur [k][n] -> int8 planes [n][k] ----------------
__global__ void __launch_bounds__(256) prep_B(const float* __restrict__ cur) {
    __shared__ float t[32][33];
    const int k0 = blockIdx.x * 32;
    const int n0 = blockIdx.y * 32;
    const int tx = threadIdx.x, ty = threadIdx.y;
    for (int i = ty; i < 32; i += 8)
        t[i][tx] = cur[(size_t)(k0 + i) * DCOLS + n0 + tx];
    __syncthreads();
    for (int i = ty; i < 32; i += 8) {
        const int n = n0 + i;
        float v = t[tx][i];
        float q = v / g_Sb[n];
        int i1 = __float2int_rn(q);
        int i2 = __float2int_rn(254.f * (q - (float)i1));
        size_t o = (size_t)n * NROWS + (size_t)(k0 + tx);
        g_B1[o] = (int8_t)i1;
        g_B2[o] = (int8_t)i2;
    }
}

// ---------------- GEMM common ------------------------------------------------
// CTA tile 128x128, 256 threads, warp grid 4(m) x 2(n), warp tile 32x64.
constexpr int BM = 128, BN = 128;

// ======== Pass 1: part = a1*b1, BK=128, planes A1/B1 only ====================
constexpr int BK1 = 128, NCH1 = NROWS / BK1;            // 64 chunks
constexpr int TILE1 = BM * BK1;                          // 16 KB per operand
constexpr int STAGE1 = 2 * TILE1;                        // 32 KB
constexpr int SMEM1 = 1024 + 3 * STAGE1;                 // 99328

__device__ __forceinline__ void load_stage1(uint32_t st, int c, int m0, int n0, int tid) {
    const size_t rs = (size_t)NROWS;
    const size_t kb = (size_t)c * BK1;
    const char* A1 = (const char*)g_A1 + (size_t)m0 * rs + kb;
    const char* B1 = (const char*)g_B1 + (size_t)n0 * rs + kb;
    #pragma unroll
    for (int i = 0; i < 4; i++) {
        int idx = i * 256 + tid, row = idx >> 3, g = idx & 7;
        cp16(st + row * 128 + ((g ^ (row & 7)) << 4), A1 + (size_t)row * rs + (size_t)g * 16);
    }
    const uint32_t bs = st + TILE1;
    #pragma unroll
    for (int i = 0; i < 4; i++) {
        int idx = i * 256 + tid, row = idx >> 3, g = idx & 7;
        cp16(bs + row * 128 + ((g ^ (row & 7)) << 4), B1 + (size_t)row * rs + (size_t)g * 16);
    }
}

__global__ void __launch_bounds__(256, 2) gemm_main() {
    extern __shared__ char smem_raw[];
    const uint32_t sb = (smem_u32(smem_raw) + 1023u) & ~1023u;
    const int tid = threadIdx.x, lane = tid & 31, w = tid >> 5;
    const int wm = w & 3, wn = w >> 2;
    const int m0 = blockIdx.y * BM, n0 = blockIdx.x * BN;

    #pragma unroll
    for (int s = 0; s < 2; s++) {
        load_stage1(sb + s * STAGE1, s, m0, n0, tid);
        asm volatile("cp.async.commit_group;" ::: "memory");
    }

    int am[2][8][4] = {};                    // 64 regs

    int aRow[2], bRow[4];
    #pragma unroll
    for (int mi = 0; mi < 2; mi++) aRow[mi] = wm * 32 + mi * 16 + (lane & 15);
    #pragma unroll
    for (int f = 0; f < 4; f++)
        bRow[f] = wn * 64 + f * 16 + ((lane >> 4) << 3) + (lane & 7);
    const int aSel = lane >> 4;
    const int bSel = (lane >> 3) & 1;

    for (int c = 0; c < NCH1; c++) {
        asm volatile("cp.async.wait_group 1;" ::: "memory");
        __syncthreads();
        if (c + 2 < NCH1) load_stage1(sb + ((c + 2) % 3) * STAGE1, c + 2, m0, n0, tid);
        asm volatile("cp.async.commit_group;" ::: "memory");

        const uint32_t st = sb + (c % 3) * STAGE1;
        const uint32_t aB = st, bB = st + TILE1;

        // register double-buffered pipeline over 8 (s,h) steps:
        // prefetch fragments for step stp+1 BEFORE issuing MMAs of step stp.
        uint32_t ah[2][8], bb[2][8];
        #pragma unroll
        for (int mi = 0; mi < 2; mi++)                       // A(s=0)
            ldsm4(&ah[0][4 * mi], aB + aRow[mi] * 128 +
                  ((aSel ^ (aRow[mi] & 7)) << 4));
        #pragma unroll
        for (int g = 0; g < 2; g++)                          // B(s=0,h=0)
            ldsm4(&bb[0][4 * g], bB + bRow[g] * 128 +
                  ((bSel ^ (bRow[g] & 7)) << 4));

        #pragma unroll
        for (int stp = 0; stp < 8; stp++) {
            const int s = stp >> 1, h = stp & 1, buf = stp & 1;
            if (stp < 7) {
                const int ns = (stp + 1) >> 1, nh = (stp + 1) & 1;
                if (nh == 0) {                               // new s: prefetch A
                    #pragma unroll
                    for (int mi = 0; mi < 2; mi++)
                        ldsm4(&ah[ns & 1][4 * mi], aB + aRow[mi] * 128 +
                              (((2 * ns + aSel) ^ (aRow[mi] & 7)) << 4));
                }
                #pragma unroll
                for (int g = 0; g < 2; g++) {                // prefetch B
                    const int f = 2 * nh + g;
                    ldsm4(&bb[(stp + 1) & 1][4 * g], bB + bRow[f] * 128 +
                          (((2 * ns + bSel) ^ (bRow[f] & 7)) << 4));
                }
            }
            #pragma unroll
            for (int mi = 0; mi < 2; mi++)
                #pragma unroll
                for (int j = 0; j < 4; j++)
                    mma_s8(am[mi][4 * h + j], &ah[s & 1][4 * mi], &bb[buf][2 * j]);
        }
    }

    // write int32 partials
    const int cw = n0 + wn * 64 + (lane & 3) * 2;
    #pragma unroll
    for (int mi = 0; mi < 2; mi++) {
        const int r0 = m0 + wm * 32 + mi * 16 + (lane >> 2);
        int* p0 = g_part + (size_t)r0 * DCOLS;
        int* p1 = g_part + (size_t)(r0 + 8) * DCOLS;
        #pragma unroll
        for (int ni = 0; ni < 8; ni++) {
            *(int2*)(p0 + cw + ni * 8) = make_int2(am[mi][ni][0], am[mi][ni][1]);
            *(int2*)(p1 + cw + ni * 8) = make_int2(am[mi][ni][2], am[mi][ni][3]);
        }
    }
}

// ======== Pass 2: ax = a2*b1 + a1*b2, BK=64, 4 planes ========================
constexpr int BK2 = 64, NCH2 = NROWS / BK2;             // 128 chunks
constexpr int A_BYTES2 = BM * 128;                       // 16 KB ([q1 64B | q2 64B])
constexpr int B_BYTES2 = BN * 128;                       // 16 KB
constexpr int STAGE2 = A_BYTES2 + B_BYTES2;              // 32 KB
constexpr int SMEM2 = 1024 + 3 * STAGE2;                 // 99328

__device__ __forceinline__ void load_stage2(uint32_t st, int c, int m0, int n0, int tid) {
    const size_t rs = (size_t)NROWS;
    const size_t kb = (size_t)c * BK2;
    const char* A1 = (const char*)g_A1 + (size_t)m0 * rs + kb;
    const char* A2 = (const char*)g_A2 + (size_t)m0 * rs + kb;
    const char* B1 = (const char*)g_B1 + (size_t)n0 * rs + kb;
    const char* B2 = (const char*)g_B2 + (size_t)n0 * rs + kb;
    #pragma unroll
    for (int i = 0; i < 4; i++) {
        int idx = i * 256 + tid, row = idx >> 3, g = idx & 7;
        const char* s = (g < 4 ? A1 : A2) + (size_t)row * rs + (size_t)(g & 3) * 16;
        cp16(st + row * 128 + ((g ^ (row & 7)) << 4), s);
    }
    const uint32_t bs = st + A_BYTES2;
    #pragma unroll
    for (int i = 0; i < 4; i++) {
        int idx = i * 256 + tid, row = idx >> 3, g = idx & 7;
        const char* s = (g < 4 ? B1 : B2) + (size_t)row * rs + (size_t)(g & 3) * 16;
        cp16(bs + row * 128 + ((g ^ (row & 7)) << 4), s);
    }
}

__global__ void __launch_bounds__(256, 2) gemm_cross(float* __restrict__ out) {
    extern __shared__ char smem_raw[];
    const uint32_t sb = (smem_u32(smem_raw) + 1023u) & ~1023u;
    const int tid = threadIdx.x, lane = tid & 31, w = tid >> 5;
    const int wm = w & 3, wn = w >> 2;
    const int m0 = blockIdx.y * BM, n0 = blockIdx.x * BN;

    #pragma unroll
    for (int s = 0; s < 2; s++) {
        load_stage2(sb + s * STAGE2, s, m0, n0, tid);
        asm volatile("cp.async.commit_group;" ::: "memory");
    }

    int ax[2][8][4] = {};                    // 64 regs

    int aRow[2], bRow[4];
    #pragma unroll
    for (int mi = 0; mi < 2; mi++) aRow[mi] = wm * 32 + mi * 16 + (lane & 15);
    #pragma unroll
    for (int f = 0; f < 4; f++)
        bRow[f] = wn * 64 + f * 16 + ((lane >> 4) << 3) + (lane & 7);
    const int aSel = lane >> 4;
    const int bSel = (lane >> 3) & 1;

    for (int c = 0; c < NCH2; c++) {
        asm volatile("cp.async.wait_group 1;" ::: "memory");
        __syncthreads();
        if (c + 2 < NCH2) load_stage2(sb + ((c + 2) % 3) * STAGE2, c + 2, m0, n0, tid);
        asm volatile("cp.async.commit_group;" ::: "memory");

        const uint32_t st = sb + (c % 3) * STAGE2;
        const uint32_t aB = st, bB = st + A_BYTES2;

        // 8 steps: (q,h,p) with p=0 -> a2*b1, p=1 -> a1*b2.
        // B fragments double-buffered (prefetch next step before MMAs);
        // A planes single-buffered, reloaded at stp==4 (after last q=0 use).
        uint32_t ah[8], al[8], bb[2][8];
        #pragma unroll
        for (int mi = 0; mi < 2; mi++) {                     // A(q=0)
            ldsm4(&ah[4 * mi], aB + aRow[mi] * 128 +
                  ((aSel ^ (aRow[mi] & 7)) << 4));
            ldsm4(&al[4 * mi], aB + aRow[mi] * 128 +
                  (((4 + aSel) ^ (aRow[mi] & 7)) << 4));
        }
        #pragma unroll
        for (int g = 0; g < 2; g++)                          // B(q0,h0,b1)
            ldsm4(&bb[0][4 * g], bB + bRow[g] * 128 +
                  ((bSel ^ (bRow[g] & 7)) << 4));

        #pragma unroll
        for (int stp = 0; stp < 8; stp++) {
            const int h = (stp >> 1) & 1, p = stp & 1, buf = stp & 1;
            if (stp == 4) {                                  // A(q=1), after q0's last use
                #pragma unroll
                for (int mi = 0; mi < 2; mi++) {
                    ldsm4(&ah[4 * mi], aB + aRow[mi] * 128 +
                          (((2 + aSel) ^ (aRow[mi] & 7)) << 4));
                    ldsm4(&al[4 * mi], aB + aRow[mi] * 128 +
                          (((6 + aSel) ^ (aRow[mi] & 7)) << 4));
                }
            }
            if (stp < 7) {                                   // prefetch next B
                const int n = stp + 1;
                const int nq = n >> 2, nh = (n >> 1) & 1, np = n & 1;
                const int ksel = (np == 0 ? 2 * nq : 4 + 2 * nq) + bSel;
                #pragma unroll
                for (int g = 0; g < 2; g++) {
                    const int f = 2 * nh + g;
                    ldsm4(&bb[n & 1][4 * g], bB + bRow[f] * 128 +
                          ((ksel ^ (bRow[f] & 7)) << 4));
                }
            }
            #pragma unroll
            for (int mi = 0; mi < 2; mi++)
                #pragma unroll
                for (int j = 0; j < 4; j++)
                    mma_s8(ax[mi][4 * h + j],
                           (p == 0 ? &al[4 * mi] : &ah[4 * mi]), &bb[buf][2 * j]);
        }
    }

    // epilogue: fea = Sa*Sb*(part + ax/254); out = fea / deg (RN)
    const float C = 1.f / 254.f;
    const int cw = n0 + wn * 64 + (lane & 3) * 2;
    #pragma unroll
    for (int mi = 0; mi < 2; mi++) {
        const int r0 = m0 + wm * 32 + mi * 16 + (lane >> 2);
        const float d0 = g_deg[r0], d1 = g_deg[r0 + 8];
        const float sa0 = g_Sa[r0], sa1 = g_Sa[r0 + 8];
        const int* q0 = g_part + (size_t)r0 * DCOLS;
        const int* q1 = g_part + (size_t)(r0 + 8) * DCOLS;
        float* p0 = out + (size_t)r0 * DCOLS;
        float* p1 = out + (size_t)(r0 + 8) * DCOLS;
        #pragma unroll
        for (int ni = 0; ni < 8; ni++) {
            const int col = cw + ni * 8;
            float2 sbv = *(const float2*)(g_Sb + col);
            int2 m0v = *(const int2*)(q0 + col);
            int2 m1v = *(const int2*)(q1 + col);
            float f00 = sa0 * sbv.x * ((float)m0v.x + (float)ax[mi][ni][0] * C);
            float f01 = sa0 * sbv.y * ((float)m0v.y + (float)ax[mi][ni][1] * C);
            float f10 = sa1 * sbv.x * ((float)m1v.x + (float)ax[mi][ni][2] * C);
            float f11 = sa1 * sbv.y * ((float)m1v.y + (float)ax[mi][ni][3] * C);
            *(float2*)(p0 + col) = make_float2(__fdiv_rn(f00, d0), __fdiv_rn(f01, d0));
            *(float2*)(p1 + col) = make_float2(__fdiv_rn(f10, d1), __fdiv_rn(f11, d1));
        }
    }
}

// ---------------- launch ----------------
extern "C" void kernel_launch(void* const* d_in, const int* in_sizes, int n_in,
                              void* d_out, int out_size) {
    const float* cur = (const float*)d_in[0];
    const float* inc = (const float*)d_in[1];
    if (n_in >= 2 && in_sizes[0] == NROWS * NROWS) {  // defensive input-order check
        inc = (const float*)d_in[0];
        cur = (const float*)d_in[1];
    }
    cudaFuncSetAttribute(gemm_main, cudaFuncAttributeMaxDynamicSharedMemorySize, SMEM1);
    cudaFuncSetAttribute(gemm_cross, cudaFuncAttributeMaxDynamicSharedMemorySize, SMEM2);

    prep_rows<<<NROWS, 256>>>(inc);
    prep_Bscale<<<DCOLS / 8, 256>>>(cur);
    prep_B<<<dim3(NROWS / 32, DCOLS / 32), dim3(32, 8)>>>(cur);
    gemm_main<<<dim3(DCOLS / BN, NROWS / BM), 256, SMEM1>>>();
    gemm_cross<<<dim3(DCOLS / BN, NROWS / BM), 256, SMEM2>>>((float*)d_out);
}

// round 12
// speedup vs baseline: 1.0309x; 1.0309x over previous
#include <cuda_runtime.h>
#include <cuda_bf16.h>
#include <cstdint>

#define NROWS 8192
#define DCOLS 512

// ---------------- scratch (device globals: allocation-free) ----------------
__device__ __align__(256) int8_t g_A1[(size_t)NROWS * NROWS];   // 64 MB
__device__ __align__(256) int8_t g_A2[(size_t)NROWS * NROWS];   // 64 MB
__device__ __align__(256) int8_t g_B1[(size_t)DCOLS * NROWS];   // 4 MB [n][k]
__device__ __align__(256) int8_t g_B2[(size_t)DCOLS * NROWS];   // 4 MB
__device__ __align__(256) int   g_part[(size_t)NROWS * DCOLS];  // 16 MB (a1*b1)
__device__ float g_deg[NROWS];
__device__ float g_Sa[NROWS];
__device__ float g_Sb[DCOLS];

// ---------------- PTX helpers (compute_100-safe: no 'a' features) ----------
__device__ __forceinline__ uint32_t smem_u32(const void* p) {
    uint32_t a;
    asm("{ .reg .u64 t; cvta.to.shared.u64 t, %1; cvt.u32.u64 %0, t; }" : "=r"(a) : "l"(p));
    return a;
}
__device__ __forceinline__ void cp16(uint32_t dst, const void* src) {
    asm volatile("cp.async.cg.shared.global [%0], [%1], 16;" :: "r"(dst), "l"(src));
}
__device__ __forceinline__ void ldsm4(uint32_t* r, uint32_t addr) {
    asm volatile("ldmatrix.sync.aligned.m8n8.x4.shared.b16 {%0,%1,%2,%3}, [%4];"
                 : "=r"(r[0]), "=r"(r[1]), "=r"(r[2]), "=r"(r[3]) : "r"(addr));
}
__device__ __forceinline__ void mma_s8(int* c, const uint32_t* a, const uint32_t* b) {
    asm("mma.sync.aligned.m16n8k32.row.col.s32.s8.s8.s32 "
        "{%0,%1,%2,%3}, {%4,%5,%6,%7}, {%8,%9}, {%0,%1,%2,%3};"
        : "+r"(c[0]), "+r"(c[1]), "+r"(c[2]), "+r"(c[3])
        : "r"(a[0]), "r"(a[1]), "r"(a[2]), "r"(a[3]), "r"(b[0]), "r"(b[1]));
}
__device__ __forceinline__ uint32_t pack4(int b0, int b1, int b2, int b3) {
    return (b0 & 0xFF) | ((b1 & 0xFF) << 8) | ((b2 & 0xFF) << 16) | ((b3 & 0xFF) << 24);
}

// ---------------- P1: row stats + XLA-order deg + int8 quant ----------------
// pass1: gmem->smem + positive count. pass2: XLA-order deg sum AND row max
// (same sweep — max is order-independent). pass3: quantize to 2 int8 planes.
__global__ void __launch_bounds__(256) prep_rows(const float* __restrict__ inc) {
    __shared__ float row[NROWS];
    __shared__ int   red_c[8];
    __shared__ float wpart[32];
    __shared__ float wmax[8];
    __shared__ float s_hv, s_inv;

    const int r = blockIdx.x;
    const int tid = threadIdx.x;
    const int lane = tid & 31, warp = tid >> 5;

    const float4* src = (const float4*)(inc + (size_t)r * NROWS);
    float4* dst = (float4*)row;
    int cnt = 0;
    for (int i = tid; i < NROWS / 4; i += 256) {
        float4 v = src[i];
        dst[i] = v;
        cnt += (v.x > 0.f) + (v.y > 0.f) + (v.z > 0.f) + (v.w > 0.f);
    }
    for (int o = 16; o; o >>= 1) cnt += __shfl_xor_sync(0xFFFFFFFFu, cnt, o);
    if (lane == 0) red_c[warp] = cnt;
    __syncthreads();
    if (tid == 0) {
        int c = 0;
        #pragma unroll
        for (int i = 0; i < 8; i++) c += red_c[i];
        float denom = __fsqrt_rn((float)c);
        denom = fmaxf(denom, 1e-12f);
        s_hv = __fdiv_rn(1.0f, denom);
    }
    __syncthreads();
    const float hv = s_hv;

    // deg (XLA-GPU order mimic) + row max, single sweep
    float accx[4], accy[4];
    float mx = 0.f;
    #pragma unroll
    for (int jv = 0; jv < 4; jv++) { accx[jv] = 0.f; accy[jv] = 0.f; }
    #pragma unroll
    for (int jv = 0; jv < 4; jv++) {
        const int vt = tid + 256 * jv;
        #pragma unroll
        for (int i = 0; i < 4; i++) {
            const int j = 2 * vt + 2048 * i;
            float x = row[j];
            float y = row[j + 1];
            if (x > 0.f) x = x + hv;
            if (y > 0.f) y = y + hv;
            accx[jv] += x;
            accy[jv] += y;
            mx = fmaxf(mx, fmaxf(fabsf(x), fabsf(y)));
        }
    }
    #pragma unroll
    for (int jv = 0; jv < 4; jv++) {
        float s = accx[jv] + accy[jv];
        s += __shfl_down_sync(0xFFFFFFFFu, s, 16);
        s += __shfl_down_sync(0xFFFFFFFFu, s, 8);
        s += __shfl_down_sync(0xFFFFFFFFu, s, 4);
        s += __shfl_down_sync(0xFFFFFFFFu, s, 2);
        s += __shfl_down_sync(0xFFFFFFFFu, s, 1);
        if (lane == 0) wpart[jv * 8 + warp] = s;
    }
    for (int o = 16; o; o >>= 1) mx = fmaxf(mx, __shfl_xor_sync(0xFFFFFFFFu, mx, o));
    if (lane == 0) wmax[warp] = mx;
    __syncthreads();
    if (tid < 32) {
        float v = wpart[tid];
        v += __shfl_down_sync(0xFFFFFFFFu, v, 16);
        v += __shfl_down_sync(0xFFFFFFFFu, v, 8);
        v += __shfl_down_sync(0xFFFFFFFFu, v, 4);
        v += __shfl_down_sync(0xFFFFFFFFu, v, 2);
        v += __shfl_down_sync(0xFFFFFFFFu, v, 1);
        if (tid == 0) g_deg[r] = v;
    }
    if (tid == 32) {                        // different warp than deg finalizer
        float m = 1e-30f;
        #pragma unroll
        for (int i = 0; i < 8; i++) m = fmaxf(m, wmax[i]);
        g_Sa[r] = m / 127.f;
        s_inv = 127.f / m;
    }
    __syncthreads();
    const float inv = s_inv;

    // quantize: a' = Sa*(q1 + q2/254)   (float4 smem reads, 16B gmem writes)
    const float4* rowv = (const float4*)row;
    uint2* p1 = (uint2*)(g_A1 + (size_t)r * NROWS);
    uint2* p2 = (uint2*)(g_A2 + (size_t)r * NROWS);
    for (int i = tid; i < NROWS / 8; i += 256) {
        float4 v0 = rowv[2 * i];
        float4 v1 = rowv[2 * i + 1];
        float a[8] = {v0.x, v0.y, v0.z, v0.w, v1.x, v1.y, v1.z, v1.w};
        int q1[8], q2[8];
        #pragma unroll
        for (int e = 0; e < 8; e++) {
            float aa = a[e];
            if (aa > 0.f) aa = aa + hv;
            float q = aa * inv;
            int i1 = __float2int_rn(q);
            int i2 = __float2int_rn(254.f * (q - (float)i1));
            q1[e] = i1; q2[e] = i2;
        }
        uint2 u1, u2;
        u1.x = pack4(q1[0], q1[1], q1[2], q1[3]);
        u1.y = pack4(q1[4], q1[5], q1[6], q1[7]);
        u2.x = pack4(q2[0], q2[1], q2[2], q2[3]);
        u2.y = pack4(q2[4], q2[5], q2[6], q2[7]);
        p1[i] = u1;
        p2[i] = u2;
    }
}

// ---------------- P2a: per-column max of cur -> g_Sb ----------------
__global__ void __launch_bounds__(256) prep_Bscale(const float* __restrict__ cur) {
    __shared__ float red[32][8];
    const int tid = threadIdx.x;
    const int nIn = tid & 7;
    const int kp = tid >> 3;
    const int n = blockIdx.x * 8 + nIn;
    float m = 0.f;
    for (int k = kp; k < NROWS; k += 32)
        m = fmaxf(m, fabsf(cur[(size_t)k * DCOLS + n]));
    red[kp][nIn] = m;
    __syncthreads();
    if (tid < 8) {
        float mm = 1e-30f;
        #pragma unroll
        for (int i = 0; i < 32; i++) mm = fmaxf(mm, red[i][tid]);
        g_Sb[blockIdx.x * 8 + tid] = mm / 127.f;
    }
}

// ---------------- P2b: cur [k][n] -> int8 planes [n][k] ----------------
__global__ void __launch_bounds__(256) prep_B(const float* __restrict__ cur) {
    __shared__ float t[32][33];
    const int k0 = blockIdx.x * 32;
    const int n0 = blockIdx.y * 32;
    const int tx = threadIdx.x, ty = threadIdx.y;
    for (int i = ty; i < 32; i += 8)
        t[i][tx] = cur[(size_t)(k0 + i) * DCOLS + n0 + tx];
    __syncthreads();
    for (int i = ty; i < 32; i += 8) {
        const int n = n0 + i;
        float v = t[tx][i];
        float q = v / g_Sb[n];
        int i1 = __float2int_rn(q);
        int i2 = __float2int_rn(254.f * (q - (float)i1));
        size_t o = (size_t)n * NROWS + (size_t)(k0 + tx);
        g_B1[o] = (int8_t)i1;
        g_B2[o] = (int8_t)i2;
    }
}

// ---------------- GEMM common ------------------------------------------------
// CTA tile 128x128, 256 threads, warp grid 4(m) x 2(n), warp tile 32x64.
constexpr int BM = 128, BN = 128;

// ======== Pass 1: part = a1*b1, BK=128, planes A1/B1 only ====================
constexpr int BK1 = 128, NCH1 = NROWS / BK1;            // 64 chunks
constexpr int TILE1 = BM * BK1;                          // 16 KB per operand
constexpr int STAGE1 = 2 * TILE1;                        // 32 KB
constexpr int SMEM1 = 1024 + 3 * STAGE1;                 // 99328

__device__ __forceinline__ void load_stage1(uint32_t st, int c, int m0, int n0, int tid) {
    const size_t rs = (size_t)NROWS;
    const size_t kb = (size_t)c * BK1;
    const char* A1 = (const char*)g_A1 + (size_t)m0 * rs + kb;
    const char* B1 = (const char*)g_B1 + (size_t)n0 * rs + kb;
    #pragma unroll
    for (int i = 0; i < 4; i++) {
        int idx = i * 256 + tid, row = idx >> 3, g = idx & 7;
        cp16(st + row * 128 + ((g ^ (row & 7)) << 4), A1 + (size_t)row * rs + (size_t)g * 16);
    }
    const uint32_t bs = st + TILE1;
    #pragma unroll
    for (int i = 0; i < 4; i++) {
        int idx = i * 256 + tid, row = idx >> 3, g = idx & 7;
        cp16(bs + row * 128 + ((g ^ (row & 7)) << 4), B1 + (size_t)row * rs + (size_t)g * 16);
    }
}

__global__ void __launch_bounds__(256, 2) gemm_main() {
    extern __shared__ char smem_raw[];
    const uint32_t sb = (smem_u32(smem_raw) + 1023u) & ~1023u;
    const int tid = threadIdx.x, lane = tid & 31, w = tid >> 5;
    const int wm = w & 3, wn = w >> 2;
    const int m0 = blockIdx.y * BM, n0 = blockIdx.x * BN;

    #pragma unroll
    for (int s = 0; s < 2; s++) {
        load_stage1(sb + s * STAGE1, s, m0, n0, tid);
        asm volatile("cp.async.commit_group;" ::: "memory");
    }

    int am[2][8][4] = {};                    // 64 regs

    int aRow[2], bRow[4];
    #pragma unroll
    for (int mi = 0; mi < 2; mi++) aRow[mi] = wm * 32 + mi * 16 + (lane & 15);
    #pragma unroll
    for (int f = 0; f < 4; f++)
        bRow[f] = wn * 64 + f * 16 + ((lane >> 4) << 3) + (lane & 7);
    const int aSel = lane >> 4;
    const int bSel = (lane >> 3) & 1;

    for (int c = 0; c < NCH1; c++) {
        asm volatile("cp.async.wait_group 1;" ::: "memory");
        __syncthreads();
        if (c + 2 < NCH1) load_stage1(sb + ((c + 2) % 3) * STAGE1, c + 2, m0, n0, tid);
        asm volatile("cp.async.commit_group;" ::: "memory");

        const uint32_t st = sb + (c % 3) * STAGE1;
        const uint32_t aB = st, bB = st + TILE1;

        #pragma unroll
        for (int s = 0; s < 4; s++) {        // four k32 steps (k128 row)
            uint32_t ah[8], bb[8];
            #pragma unroll
            for (int mi = 0; mi < 2; mi++)
                ldsm4(&ah[4 * mi], aB + aRow[mi] * 128 +
                      (((2 * s + aSel) ^ (aRow[mi] & 7)) << 4));
            #pragma unroll
            for (int h = 0; h < 2; h++) {
                #pragma unroll
                for (int g = 0; g < 2; g++) {
                    const int f = 2 * h + g;
                    ldsm4(&bb[4 * g], bB + bRow[f] * 128 +
                          (((2 * s + bSel) ^ (bRow[f] & 7)) << 4));
                }
                #pragma unroll
                for (int mi = 0; mi < 2; mi++)
                    #pragma unroll
                    for (int j = 0; j < 4; j++)
                        mma_s8(am[mi][4 * h + j], &ah[4 * mi], &bb[2 * j]);
            }
        }
    }

    // write int32 partials
    const int cw = n0 + wn * 64 + (lane & 3) * 2;
    #pragma unroll
    for (int mi = 0; mi < 2; mi++) {
        const int r0 = m0 + wm * 32 + mi * 16 + (lane >> 2);
        int* p0 = g_part + (size_t)r0 * DCOLS;
        int* p1 = g_part + (size_t)(r0 + 8) * DCOLS;
        #pragma unroll
        for (int ni = 0; ni < 8; ni++) {
            *(int2*)(p0 + cw + ni * 8) = make_int2(am[mi][ni][0], am[mi][ni][1]);
            *(int2*)(p1 + cw + ni * 8) = make_int2(am[mi][ni][2], am[mi][ni][3]);
        }
    }
}

// ======== Pass 2: ax = a2*b1 + a1*b2, BK=64, 4 planes ========================
constexpr int BK2 = 64, NCH2 = NROWS / BK2;             // 128 chunks
constexpr int A_BYTES2 = BM * 128;                       // 16 KB ([q1 64B | q2 64B])
constexpr int B_BYTES2 = BN * 128;                       // 16 KB
constexpr int STAGE2 = A_BYTES2 + B_BYTES2;              // 32 KB
constexpr int SMEM2 = 1024 + 3 * STAGE2;                 // 99328

__device__ __forceinline__ void load_stage2(uint32_t st, int c, int m0, int n0, int tid) {
    const size_t rs = (size_t)NROWS;
    const size_t kb = (size_t)c * BK2;
    const char* A1 = (const char*)g_A1 + (size_t)m0 * rs + kb;
    const char* A2 = (const char*)g_A2 + (size_t)m0 * rs + kb;
    const char* B1 = (const char*)g_B1 + (size_t)n0 * rs + kb;
    const char* B2 = (const char*)g_B2 + (size_t)n0 * rs + kb;
    #pragma unroll
    for (int i = 0; i < 4; i++) {
        int idx = i * 256 + tid, row = idx >> 3, g = idx & 7;
        const char* s = (g < 4 ? A1 : A2) + (size_t)row * rs + (size_t)(g & 3) * 16;
        cp16(st + row * 128 + ((g ^ (row & 7)) << 4), s);
    }
    const uint32_t bs = st + A_BYTES2;
    #pragma unroll
    for (int i = 0; i < 4; i++) {
        int idx = i * 256 + tid, row = idx >> 3, g = idx & 7;
        const char* s = (g < 4 ? B1 : B2) + (size_t)row * rs + (size_t)(g & 3) * 16;
        cp16(bs + row * 128 + ((g ^ (row & 7)) << 4), s);
    }
}

__global__ void __launch_bounds__(256, 2) gemm_cross(float* __restrict__ out) {
    extern __shared__ char smem_raw[];
    const uint32_t sb = (smem_u32(smem_raw) + 1023u) & ~1023u;
    const int tid = threadIdx.x, lane = tid & 31, w = tid >> 5;
    const int wm = w & 3, wn = w >> 2;
    const int m0 = blockIdx.y * BM, n0 = blockIdx.x * BN;

    #pragma unroll
    for (int s = 0; s < 2; s++) {
        load_stage2(sb + s * STAGE2, s, m0, n0, tid);
        asm volatile("cp.async.commit_group;" ::: "memory");
    }

    int ax[2][8][4] = {};                    // 64 regs

    int aRow[2], bRow[4];
    #pragma unroll
    for (int mi = 0; mi < 2; mi++) aRow[mi] = wm * 32 + mi * 16 + (lane & 15);
    #pragma unroll
    for (int f = 0; f < 4; f++)
        bRow[f] = wn * 64 + f * 16 + ((lane >> 4) << 3) + (lane & 7);
    const int aSel = lane >> 4;
    const int bSel = (lane >> 3) & 1;

    for (int c = 0; c < NCH2; c++) {
        asm volatile("cp.async.wait_group 1;" ::: "memory");
        __syncthreads();
        if (c + 2 < NCH2) load_stage2(sb + ((c + 2) % 3) * STAGE2, c + 2, m0, n0, tid);
        asm volatile("cp.async.commit_group;" ::: "memory");

        const uint32_t st = sb + (c % 3) * STAGE2;
        const uint32_t aB = st, bB = st + A_BYTES2;

        #pragma unroll
        for (int q = 0; q < 2; q++) {        // two k32 steps
            uint32_t ah[8], al[8], bb[8];
            #pragma unroll
            for (int mi = 0; mi < 2; mi++) {
                ldsm4(&ah[4 * mi], aB + aRow[mi] * 128 +
                      (((q * 2 + aSel) ^ (aRow[mi] & 7)) << 4));     // plane q1
                ldsm4(&al[4 * mi], aB + aRow[mi] * 128 +
                      (((4 + q * 2 + aSel) ^ (aRow[mi] & 7)) << 4)); // plane q2
            }
            #pragma unroll
            for (int h = 0; h < 2; h++) {
                #pragma unroll
                for (int g = 0; g < 2; g++) {        // b1
                    const int f = 2 * h + g;
                    ldsm4(&bb[4 * g], bB + bRow[f] * 128 +
                          (((q * 2 + bSel) ^ (bRow[f] & 7)) << 4));
                }
                #pragma unroll
                for (int mi = 0; mi < 2; mi++)
                    #pragma unroll
                    for (int j = 0; j < 4; j++)
                        mma_s8(ax[mi][4 * h + j], &al[4 * mi], &bb[2 * j]);  // a2*b1
                #pragma unroll
                for (int g = 0; g < 2; g++) {        // b2 overwrites
                    const int f = 2 * h + g;
                    ldsm4(&bb[4 * g], bB + bRow[f] * 128 +
                          (((4 + q * 2 + bSel) ^ (bRow[f] & 7)) << 4));
                }
                #pragma unroll
                for (int mi = 0; mi < 2; mi++)
                    #pragma unroll
                    for (int j = 0; j < 4; j++)
                        mma_s8(ax[mi][4 * h + j], &ah[4 * mi], &bb[2 * j]);  // a1*b2
            }
        }
    }

    // epilogue: fea = Sa*Sb*(part + ax/254); out = fea / deg (RN)
    const float C = 1.f / 254.f;
    const int cw = n0 + wn * 64 + (lane & 3) * 2;
    #pragma unroll
    for (int mi = 0; mi < 2; mi++) {
        const int r0 = m0 + wm * 32 + mi * 16 + (lane >> 2);
        const float d0 = g_deg[r0], d1 = g_deg[r0 + 8];
        const float sa0 = g_Sa[r0], sa1 = g_Sa[r0 + 8];
        const int* q0 = g_part + (size_t)r0 * DCOLS;
        const int* q1 = g_part + (size_t)(r0 + 8) * DCOLS;
        float* p0 = out + (size_t)r0 * DCOLS;
        float* p1 = out + (size_t)(r0 + 8) * DCOLS;
        #pragma unroll
        for (int ni = 0; ni < 8; ni++) {
            const int col = cw + ni * 8;
            float2 sbv = *(const float2*)(g_Sb + col);
            int2 m0v = *(const int2*)(q0 + col);
            int2 m1v = *(const int2*)(q1 + col);
            float f00 = sa0 * sbv.x * ((float)m0v.x + (float)ax[mi][ni][0] * C);
            float f01 = sa0 * sbv.y * ((float)m0v.y + (float)ax[mi][ni][1] * C);
            float f10 = sa1 * sbv.x * ((float)m1v.x + (float)ax[mi][ni][2] * C);
            float f11 = sa1 * sbv.y * ((float)m1v.y + (float)ax[mi][ni][3] * C);
            *(float2*)(p0 + col) = make_float2(__fdiv_rn(f00, d0), __fdiv_rn(f01, d0));
            *(float2*)(p1 + col) = make_float2(__fdiv_rn(f10, d1), __fdiv_rn(f11, d1));
        }
    }
}

// ---------------- launch ----------------
extern "C" void kernel_launch(void* const* d_in, const int* in_sizes, int n_in,
                              void* d_out, int out_size) {
    const float* cur = (const float*)d_in[0];
    const float* inc = (const float*)d_in[1];
    if (n_in >= 2 && in_sizes[0] == NROWS * NROWS) {  // defensive input-order check
        inc = (const float*)d_in[0];
        cur = (const float*)d_in[1];
    }
    cudaFuncSetAttribute(gemm_main, cudaFuncAttributeMaxDynamicSharedMemorySize, SMEM1);
    cudaFuncSetAttribute(gemm_cross, cudaFuncAttributeMaxDynamicSharedMemorySize, SMEM2);

    prep_rows<<<NROWS, 256>>>(inc);
    prep_Bscale<<<DCOLS / 8, 256>>>(cur);
    prep_B<<<dim3(NROWS / 32, DCOLS / 32), dim3(32, 8)>>>(cur);
    gemm_main<<<dim3(DCOLS / BN, NROWS / BM), 256, SMEM1>>>();
    gemm_cross<<<dim3(DCOLS / BN, NROWS / BM), 256, SMEM2>>>((float*)d_out);
}

// round 13
// speedup vs baseline: 1.1105x; 1.0772x over previous
#include <cuda_runtime.h>
#include <cuda_bf16.h>
#include <cstdint>

#define NROWS 8192
#define DCOLS 512

// ---------------- scratch (device globals: allocation-free) ----------------
__device__ __align__(256) int8_t g_A1[(size_t)NROWS * NROWS];   // 64 MB
__device__ __align__(256) int8_t g_A2[(size_t)NROWS * NROWS];   // 64 MB
__device__ __align__(256) int8_t g_B1[(size_t)DCOLS * NROWS];   // 4 MB [n][k]
__device__ __align__(256) int8_t g_B2[(size_t)DCOLS * NROWS];   // 4 MB
__device__ __align__(256) int   g_part[(size_t)NROWS * DCOLS];  // 16 MB (a1*b1)
__device__ float g_deg[NROWS];
__device__ float g_Sa[NROWS];
__device__ float g_Sb[DCOLS];

// ---------------- PTX helpers (compute_100-safe: no 'a' features) ----------
__device__ __forceinline__ uint32_t smem_u32(const void* p) {
    uint32_t a;
    asm("{ .reg .u64 t; cvta.to.shared.u64 t, %1; cvt.u32.u64 %0, t; }" : "=r"(a) : "l"(p));
    return a;
}
__device__ __forceinline__ void cp16(uint32_t dst, const void* src) {
    asm volatile("cp.async.cg.shared.global [%0], [%1], 16;" :: "r"(dst), "l"(src));
}
__device__ __forceinline__ void ldsm4(uint32_t* r, uint32_t addr) {
    asm volatile("ldmatrix.sync.aligned.m8n8.x4.shared.b16 {%0,%1,%2,%3}, [%4];"
                 : "=r"(r[0]), "=r"(r[1]), "=r"(r[2]), "=r"(r[3]) : "r"(addr));
}
__device__ __forceinline__ void mma_s8(int* c, const uint32_t* a, const uint32_t* b) {
    asm("mma.sync.aligned.m16n8k32.row.col.s32.s8.s8.s32 "
        "{%0,%1,%2,%3}, {%4,%5,%6,%7}, {%8,%9}, {%0,%1,%2,%3};"
        : "+r"(c[0]), "+r"(c[1]), "+r"(c[2]), "+r"(c[3])
        : "r"(a[0]), "r"(a[1]), "r"(a[2]), "r"(a[3]), "r"(b[0]), "r"(b[1]));
}

// ---------------- P1: row stats + XLA-order deg + int8 quant ----------------
// Single streaming pass: load row as float2 in XLA thread order (registers),
// count positives + max/min in the same pass, then deg (XLA order, from regs),
// then quantize from regs. No smem data array.
__global__ void __launch_bounds__(256) prep_rows(const float* __restrict__ inc) {
    __shared__ int   red_c[8];
    __shared__ float red_mp[8];
    __shared__ float red_mn[8];
    __shared__ float wpart[32];
    __shared__ float s_hv, s_inv;

    const int r = blockIdx.x;
    const int tid = threadIdx.x;
    const int lane = tid & 31, warp = tid >> 5;
    const float2* src = (const float2*)(inc + (size_t)r * NROWS);

    // load 16 float2 in XLA order: pair p = tid + 256*jv + 1024*i
    float vx[16], vy[16];
    int cnt = 0;
    float mp = 0.f;     // max value (>=0; >0 iff a positive exists)
    float mn = 0.f;     // min value (<=0)
    #pragma unroll
    for (int jv = 0; jv < 4; jv++) {
        #pragma unroll
        for (int i = 0; i < 4; i++) {
            const int p = tid + 256 * jv + 1024 * i;
            float2 v = src[p];
            vx[jv * 4 + i] = v.x;
            vy[jv * 4 + i] = v.y;
            cnt += (v.x > 0.f) + (v.y > 0.f);
            mp = fmaxf(mp, fmaxf(v.x, v.y));
            mn = fminf(mn, fminf(v.x, v.y));
        }
    }
    for (int o = 16; o; o >>= 1) {
        cnt += __shfl_xor_sync(0xFFFFFFFFu, cnt, o);
        mp = fmaxf(mp, __shfl_xor_sync(0xFFFFFFFFu, mp, o));
        mn = fminf(mn, __shfl_xor_sync(0xFFFFFFFFu, mn, o));
    }
    if (lane == 0) { red_c[warp] = cnt; red_mp[warp] = mp; red_mn[warp] = mn; }
    __syncthreads();
    if (tid == 0) {
        int c = 0;
        float MP = 0.f, MN = 0.f;
        #pragma unroll
        for (int i = 0; i < 8; i++) {
            c += red_c[i];
            MP = fmaxf(MP, red_mp[i]);
            MN = fminf(MN, red_mn[i]);
        }
        float denom = __fsqrt_rn((float)c);
        denom = fmaxf(denom, 1e-12f);
        float hv = __fdiv_rn(1.0f, denom);
        s_hv = hv;
        // max|a'| = max(fl(maxpos+hv), -minneg); exact (fp add monotone)
        float m = fmaxf((MP > 0.f) ? (MP + hv) : 0.f, -MN);
        m = fmaxf(m, 1e-30f);
        g_Sa[r] = m / 127.f;
        s_inv = 127.f / m;
    }
    __syncthreads();
    const float hv = s_hv;
    const float inv = s_inv;

    // deg: XLA-GPU row-reduce order mimic, from registers
    #pragma unroll
    for (int jv = 0; jv < 4; jv++) {
        float ax = 0.f, ay = 0.f;
        #pragma unroll
        for (int i = 0; i < 4; i++) {
            float x = vx[jv * 4 + i];
            float y = vy[jv * 4 + i];
            if (x > 0.f) x = x + hv;
            if (y > 0.f) y = y + hv;
            ax += x;
            ay += y;
        }
        float s = ax + ay;
        s += __shfl_down_sync(0xFFFFFFFFu, s, 16);
        s += __shfl_down_sync(0xFFFFFFFFu, s, 8);
        s += __shfl_down_sync(0xFFFFFFFFu, s, 4);
        s += __shfl_down_sync(0xFFFFFFFFu, s, 2);
        s += __shfl_down_sync(0xFFFFFFFFu, s, 1);
        if (lane == 0) wpart[jv * 8 + warp] = s;
    }
    __syncthreads();
    if (tid < 32) {
        float v = wpart[tid];
        v += __shfl_down_sync(0xFFFFFFFFu, v, 16);
        v += __shfl_down_sync(0xFFFFFFFFu, v, 8);
        v += __shfl_down_sync(0xFFFFFFFFu, v, 4);
        v += __shfl_down_sync(0xFFFFFFFFu, v, 2);
        v += __shfl_down_sync(0xFFFFFFFFu, v, 1);
        if (tid == 0) g_deg[r] = v;
    }

    // quantize from registers: a' = Sa*(q1 + q2/254); char2 stores (64B/warp)
    int8_t* A1 = g_A1 + (size_t)r * NROWS;
    int8_t* A2 = g_A2 + (size_t)r * NROWS;
    #pragma unroll
    for (int jv = 0; jv < 4; jv++) {
        #pragma unroll
        for (int i = 0; i < 4; i++) {
            const int j = 2 * tid + 512 * jv + 2048 * i;
            float x = vx[jv * 4 + i];
            float y = vy[jv * 4 + i];
            if (x > 0.f) x = x + hv;
            if (y > 0.f) y = y + hv;
            float qx = x * inv, qy = y * inv;
            int i1x = __float2int_rn(qx);
            int i1y = __float2int_rn(qy);
            int i2x = __float2int_rn(254.f * (qx - (float)i1x));
            int i2y = __float2int_rn(254.f * (qy - (float)i1y));
            *(char2*)(A1 + j) = make_char2((char)i1x, (char)i1y);
            *(char2*)(A2 + j) = make_char2((char)i2x, (char)i2y);
        }
    }
}

// ---------------- P2a: per-column max of cur -> g_Sb ----------------
__global__ void __launch_bounds__(256) prep_Bscale(const float* __restrict__ cur) {
    __shared__ float red[32][8];
    const int tid = threadIdx.x;
    const int nIn = tid & 7;
    const int kp = tid >> 3;
    const int n = blockIdx.x * 8 + nIn;
    float m = 0.f;
    for (int k = kp; k < NROWS; k += 32)
        m = fmaxf(m, fabsf(cur[(size_t)k * DCOLS + n]));
    red[kp][nIn] = m;
    __syncthreads();
    if (tid < 8) {
        float mm = 1e-30f;
        #pragma unroll
        for (int i = 0; i < 32; i++) mm = fmaxf(mm, red[i][tid]);
        g_Sb[blockIdx.x * 8 + tid] = mm / 127.f;
    }
}

// ---------------- P2b: cur [k][n] -> int8 planes [n][k] ----------------
__global__ void __launch_bounds__(256) prep_B(const float* __restrict__ cur) {
    __shared__ float t[32][33];
    const int k0 = blockIdx.x * 32;
    const int n0 = blockIdx.y * 32;
    const int tx = threadIdx.x, ty = threadIdx.y;
    for (int i = ty; i < 32; i += 8)
        t[i][tx] = cur[(size_t)(k0 + i) * DCOLS + n0 + tx];
    __syncthreads();
    for (int i = ty; i < 32; i += 8) {
        const int n = n0 + i;
        float v = t[tx][i];
        float q = v / g_Sb[n];
        int i1 = __float2int_rn(q);
        int i2 = __float2int_rn(254.f * (q - (float)i1));
        size_t o = (size_t)n * NROWS + (size_t)(k0 + tx);
        g_B1[o] = (int8_t)i1;
        g_B2[o] = (int8_t)i2;
    }
}

// ---------------- GEMM common ------------------------------------------------
// CTA tile 128x128, 256 threads, warp grid 4(m) x 2(n), warp tile 32x64.
constexpr int BM = 128, BN = 128;

// ======== Pass 1: part = a1*b1, BK=128, planes A1/B1 only ====================
constexpr int BK1 = 128, NCH1 = NROWS / BK1;            // 64 chunks
constexpr int TILE1 = BM * BK1;                          // 16 KB per operand
constexpr int STAGE1 = 2 * TILE1;                        // 32 KB
constexpr int SMEM1 = 1024 + 3 * STAGE1;                 // 99328

__device__ __forceinline__ void load_stage1(uint32_t st, int c, int m0, int n0, int tid) {
    const size_t rs = (size_t)NROWS;
    const size_t kb = (size_t)c * BK1;
    const char* A1 = (const char*)g_A1 + (size_t)m0 * rs + kb;
    const char* B1 = (const char*)g_B1 + (size_t)n0 * rs + kb;
    #pragma unroll
    for (int i = 0; i < 4; i++) {
        int idx = i * 256 + tid, row = idx >> 3, g = idx & 7;
        cp16(st + row * 128 + ((g ^ (row & 7)) << 4), A1 + (size_t)row * rs + (size_t)g * 16);
    }
    const uint32_t bs = st + TILE1;
    #pragma unroll
    for (int i = 0; i < 4; i++) {
        int idx = i * 256 + tid, row = idx >> 3, g = idx & 7;
        cp16(bs + row * 128 + ((g ^ (row & 7)) << 4), B1 + (size_t)row * rs + (size_t)g * 16);
    }
}

__global__ void __launch_bounds__(256, 2) gemm_main() {
    extern __shared__ char smem_raw[];
    const uint32_t sb = (smem_u32(smem_raw) + 1023u) & ~1023u;
    const int tid = threadIdx.x, lane = tid & 31, w = tid >> 5;
    const int wm = w & 3, wn = w >> 2;
    const int m0 = blockIdx.y * BM, n0 = blockIdx.x * BN;

    #pragma unroll
    for (int s = 0; s < 2; s++) {
        load_stage1(sb + s * STAGE1, s, m0, n0, tid);
        asm volatile("cp.async.commit_group;" ::: "memory");
    }

    int am[2][8][4] = {};                    // 64 regs

    int aRow[2], bRow[4];
    #pragma unroll
    for (int mi = 0; mi < 2; mi++) aRow[mi] = wm * 32 + mi * 16 + (lane & 15);
    #pragma unroll
    for (int f = 0; f < 4; f++)
        bRow[f] = wn * 64 + f * 16 + ((lane >> 4) << 3) + (lane & 7);
    const int aSel = lane >> 4;
    const int bSel = (lane >> 3) & 1;

    for (int c = 0; c < NCH1; c++) {
        asm volatile("cp.async.wait_group 1;" ::: "memory");
        __syncthreads();
        if (c + 2 < NCH1) load_stage1(sb + ((c + 2) % 3) * STAGE1, c + 2, m0, n0, tid);
        asm volatile("cp.async.commit_group;" ::: "memory");

        const uint32_t st = sb + (c % 3) * STAGE1;
        const uint32_t aB = st, bB = st + TILE1;

        #pragma unroll
        for (int s = 0; s < 4; s++) {        // four k32 steps (k128 row)
            uint32_t ah[8], bb[8];
            #pragma unroll
            for (int mi = 0; mi < 2; mi++)
                ldsm4(&ah[4 * mi], aB + aRow[mi] * 128 +
                      (((2 * s + aSel) ^ (aRow[mi] & 7)) << 4));
            #pragma unroll
            for (int h = 0; h < 2; h++) {
                #pragma unroll
                for (int g = 0; g < 2; g++) {
                    const int f = 2 * h + g;
                    ldsm4(&bb[4 * g], bB + bRow[f] * 128 +
                          (((2 * s + bSel) ^ (bRow[f] & 7)) << 4));
                }
                #pragma unroll
                for (int mi = 0; mi < 2; mi++)
                    #pragma unroll
                    for (int j = 0; j < 4; j++)
                        mma_s8(am[mi][4 * h + j], &ah[4 * mi], &bb[2 * j]);
            }
        }
    }

    // write int32 partials
    const int cw = n0 + wn * 64 + (lane & 3) * 2;
    #pragma unroll
    for (int mi = 0; mi < 2; mi++) {
        const int r0 = m0 + wm * 32 + mi * 16 + (lane >> 2);
        int* p0 = g_part + (size_t)r0 * DCOLS;
        int* p1 = g_part + (size_t)(r0 + 8) * DCOLS;
        #pragma unroll
        for (int ni = 0; ni < 8; ni++) {
            *(int2*)(p0 + cw + ni * 8) = make_int2(am[mi][ni][0], am[mi][ni][1]);
            *(int2*)(p1 + cw + ni * 8) = make_int2(am[mi][ni][2], am[mi][ni][3]);
        }
    }
}

// ======== Pass 2: ax = a2*b1 + a1*b2, BK=64, 4 planes ========================
constexpr int BK2 = 64, NCH2 = NROWS / BK2;             // 128 chunks
constexpr int A_BYTES2 = BM * 128;                       // 16 KB ([q1 64B | q2 64B])
constexpr int B_BYTES2 = BN * 128;                       // 16 KB
constexpr int STAGE2 = A_BYTES2 + B_BYTES2;              // 32 KB
constexpr int SMEM2 = 1024 + 3 * STAGE2;                 // 99328

__device__ __forceinline__ void load_stage2(uint32_t st, int c, int m0, int n0, int tid) {
    const size_t rs = (size_t)NROWS;
    const size_t kb = (size_t)c * BK2;
    const char* A1 = (const char*)g_A1 + (size_t)m0 * rs + kb;
    const char* A2 = (const char*)g_A2 + (size_t)m0 * rs + kb;
    const char* B1 = (const char*)g_B1 + (size_t)n0 * rs + kb;
    const char* B2 = (const char*)g_B2 + (size_t)n0 * rs + kb;
    #pragma unroll
    for (int i = 0; i < 4; i++) {
        int idx = i * 256 + tid, row = idx >> 3, g = idx & 7;
        const char* s = (g < 4 ? A1 : A2) + (size_t)row * rs + (size_t)(g & 3) * 16;
        cp16(st + row * 128 + ((g ^ (row & 7)) << 4), s);
    }
    const uint32_t bs = st + A_BYTES2;
    #pragma unroll
    for (int i = 0; i < 4; i++) {
        int idx = i * 256 + tid, row = idx >> 3, g = idx & 7;
        const char* s = (g < 4 ? B1 : B2) + (size_t)row * rs + (size_t)(g & 3) * 16;
        cp16(bs + row * 128 + ((g ^ (row & 7)) << 4), s);
    }
}

__global__ void __launch_bounds__(256, 2) gemm_cross(float* __restrict__ out) {
    extern __shared__ char smem_raw[];
    const uint32_t sb = (smem_u32(smem_raw) + 1023u) & ~1023u;
    const int tid = threadIdx.x, lane = tid & 31, w = tid >> 5;
    const int wm = w & 3, wn = w >> 2;
    const int m0 = blockIdx.y * BM, n0 = blockIdx.x * BN;

    #pragma unroll
    for (int s = 0; s < 2; s++) {
        load_stage2(sb + s * STAGE2, s, m0, n0, tid);
        asm volatile("cp.async.commit_group;" ::: "memory");
    }

    int ax[2][8][4] = {};                    // 64 regs

    int aRow[2], bRow[4];
    #pragma unroll
    for (int mi = 0; mi < 2; mi++) aRow[mi] = wm * 32 + mi * 16 + (lane & 15);
    #pragma unroll
    for (int f = 0; f < 4; f++)
        bRow[f] = wn * 64 + f * 16 + ((lane >> 4) << 3) + (lane & 7);
    const int aSel = lane >> 4;
    const int bSel = (lane >> 3) & 1;

    for (int c = 0; c < NCH2; c++) {
        asm volatile("cp.async.wait_group 1;" ::: "memory");
        __syncthreads();
        if (c + 2 < NCH2) load_stage2(sb + ((c + 2) % 3) * STAGE2, c + 2, m0, n0, tid);
        asm volatile("cp.async.commit_group;" ::: "memory");

        const uint32_t st = sb + (c % 3) * STAGE2;
        const uint32_t aB = st, bB = st + A_BYTES2;

        #pragma unroll
        for (int q = 0; q < 2; q++) {        // two k32 steps
            uint32_t ah[8], al[8], bb[8];
            #pragma unroll
            for (int mi = 0; mi < 2; mi++) {
                ldsm4(&ah[4 * mi], aB + aRow[mi] * 128 +
                      (((q * 2 + aSel) ^ (aRow[mi] & 7)) << 4));     // plane q1
                ldsm4(&al[4 * mi], aB + aRow[mi] * 128 +
                      (((4 + q * 2 + aSel) ^ (aRow[mi] & 7)) << 4)); // plane q2
            }
            #pragma unroll
            for (int h = 0; h < 2; h++) {
                #pragma unroll
                for (int g = 0; g < 2; g++) {        // b1
                    const int f = 2 * h + g;
                    ldsm4(&bb[4 * g], bB + bRow[f] * 128 +
                          (((q * 2 + bSel) ^ (bRow[f] & 7)) << 4));
                }
                #pragma unroll
                for (int mi = 0; mi < 2; mi++)
                    #pragma unroll
                    for (int j = 0; j < 4; j++)
                        mma_s8(ax[mi][4 * h + j], &al[4 * mi], &bb[2 * j]);  // a2*b1
                #pragma unroll
                for (int g = 0; g < 2; g++) {        // b2 overwrites
                    const int f = 2 * h + g;
                    ldsm4(&bb[4 * g], bB + bRow[f] * 128 +
                          (((4 + q * 2 + bSel) ^ (bRow[f] & 7)) << 4));
                }
                #pragma unroll
                for (int mi = 0; mi < 2; mi++)
                    #pragma unroll
                    for (int j = 0; j < 4; j++)
                        mma_s8(ax[mi][4 * h + j], &ah[4 * mi], &bb[2 * j]);  // a1*b2
            }
        }
    }

    // epilogue: fea = Sa*Sb*(part + ax/254); out = fea / deg (RN)
    const float C = 1.f / 254.f;
    const int cw = n0 + wn * 64 + (lane & 3) * 2;
    #pragma unroll
    for (int mi = 0; mi < 2; mi++) {
        const int r0 = m0 + wm * 32 + mi * 16 + (lane >> 2);
        const float d0 = g_deg[r0], d1 = g_deg[r0 + 8];
        const float sa0 = g_Sa[r0], sa1 = g_Sa[r0 + 8];
        const int* q0 = g_part + (size_t)r0 * DCOLS;
        const int* q1 = g_part + (size_t)(r0 + 8) * DCOLS;
        float* p0 = out + (size_t)r0 * DCOLS;
        float* p1 = out + (size_t)(r0 + 8) * DCOLS;
        #pragma unroll
        for (int ni = 0; ni < 8; ni++) {
            const int col = cw + ni * 8;
            float2 sbv = *(const float2*)(g_Sb + col);
            int2 m0v = *(const int2*)(q0 + col);
            int2 m1v = *(const int2*)(q1 + col);
            float f00 = sa0 * sbv.x * ((float)m0v.x + (float)ax[mi][ni][0] * C);
            float f01 = sa0 * sbv.y * ((float)m0v.y + (float)ax[mi][ni][1] * C);
            float f10 = sa1 * sbv.x * ((float)m1v.x + (float)ax[mi][ni][2] * C);
            float f11 = sa1 * sbv.y * ((float)m1v.y + (float)ax[mi][ni][3] * C);
            *(float2*)(p0 + col) = make_float2(__fdiv_rn(f00, d0), __fdiv_rn(f01, d0));
            *(float2*)(p1 + col) = make_float2(__fdiv_rn(f10, d1), __fdiv_rn(f11, d1));
        }
    }
}

// ---------------- launch ----------------
extern "C" void kernel_launch(void* const* d_in, const int* in_sizes, int n_in,
                              void* d_out, int out_size) {
    const float* cur = (const float*)d_in[0];
    const float* inc = (const float*)d_in[1];
    if (n_in >= 2 && in_sizes[0] == NROWS * NROWS) {  // defensive input-order check
        inc = (const float*)d_in[0];
        cur = (const float*)d_in[1];
    }
    cudaFuncSetAttribute(gemm_main, cudaFuncAttributeMaxDynamicSharedMemorySize, SMEM1);
    cudaFuncSetAttribute(gemm_cross, cudaFuncAttributeMaxDynamicSharedMemorySize, SMEM2);

    prep_rows<<<NROWS, 256>>>(inc);
    prep_Bscale<<<DCOLS / 8, 256>>>(cur);
    prep_B<<<dim3(NROWS / 32, DCOLS / 32), dim3(32, 8)>>>(cur);
    gemm_main<<<dim3(DCOLS / BN, NROWS / BM), 256, SMEM1>>>();
    gemm_cross<<<dim3(DCOLS / BN, NROWS / BM), 256, SMEM2>>>((float*)d_out);
}